// round 6
// baseline (speedup 1.0000x reference)
#include <cuda_runtime.h>

// Fixed problem structure:
//   4 nodes/graph (nodes 0..2 = jet, node 3 = muon)
//   12 directed edges/graph, edge (i,j) index within graph = 3*i + (j - (j>i))
//   H = 16, MH = 64.
// Mapping: warp = 8 groups of 4 lanes; group j handles graphs base+{j,j+8,j+16,j+24}
// (NV=4), so each 16B shared weight load feeds 4 graphs x 2 FFMA2 = LDS/FMA balance.
// All inner products use packed f32x2 FFMA along the output-dim axis.

#define NTHREADS 256
#define NV 4

typedef unsigned long long u64;

// ---- shared memory layout (floats) ----
#define JE_W1 0      // 80
#define JE_B1 80     // 16
#define JE_W2 96     // 256
#define JE_B2 352    // 16
#define MU_W1 368    // 80
#define MU_B1 448    // 16
#define MU_W2 464    // 256
#define MU_B2 720    // 16
#define L1_W  736    // 64
#define L1_B  800    // 16
#define M1_W1 816    // 1024
#define M1_B1 1840   // 64
#define M1_W2 1904   // 1024
#define M1_B2 2928   // 16
#define L2_W  2944   // 64
#define L2_B  3008   // 16
#define M2_W1 3024   // 1024
#define M2_B1 4048   // 64
#define M2_W2 4112   // 1024
#define M2_B2 5136   // 16
#define FC_W1 5152   // 2048
#define FC_B1 7200   // 64
#define FC_W2 7264   // 64
#define SMEM_FLOATS 7328

struct Params {
    const float* x;
    const float* ea;
    const float* w[24];   // je_w1..fc_b2 in metadata order
    float* out;
    int G;
};

// ---- packed f32x2 helpers ----
__device__ __forceinline__ u64 pk(float lo, float hi) {
    u64 r; asm("mov.b64 %0,{%1,%2};" : "=l"(r) : "f"(lo), "f"(hi)); return r;
}
__device__ __forceinline__ void up(u64 v, float& lo, float& hi) {
    asm("mov.b64 {%0,%1},%2;" : "=f"(lo), "=f"(hi) : "l"(v));
}
__device__ __forceinline__ u64 f2(u64 a, u64 b, u64 c) {  // a*b+c elementwise
    u64 d; asm("fma.rn.f32x2 %0,%1,%2,%3;" : "=l"(d) : "l"(a), "l"(b), "l"(c)); return d;
}
__device__ __forceinline__ u64 a2(u64 a, u64 b) {
    u64 d; asm("add.rn.f32x2 %0,%1,%2;" : "=l"(d) : "l"(a), "l"(b)); return d;
}
__device__ __forceinline__ u64 r2(u64 a) {   // relu both halves
    float l, h; up(a, l, h);
    return pk(fmaxf(l, 0.f), fmaxf(h, 0.f));
}
__device__ __forceinline__ ulonglong2 ld2(const float* p) {  // LDS.128 -> 2 packed pairs
    return *reinterpret_cast<const ulonglong2*>(p);
}

// one GINE layer + LN + relu for NV graphs; h (packed dim-pairs) updated in place.
__device__ __forceinline__ void gineN(
    u64 h[NV][8], int lane, int node,
    const float* __restrict__ ea, const int* gc,
    const float* lw, const float* lb,
    const float* w1, const float* b1,
    const float* w2, const float* b2)
{
    u64 agg[NV][8];
#pragma unroll
    for (int nv = 0; nv < NV; nv++)
#pragma unroll
        for (int j = 0; j < 8; j++) agg[nv][j] = 0ull;

#pragma unroll
    for (int m = 1; m < 4; m++) {
        int src = (node + m) & 3;
        int eidx = src * 3 + node - (node > src ? 1 : 0);
        int sl = (lane & ~3) | src;
        float ef[NV][4];
#pragma unroll
        for (int nv = 0; nv < NV; nv++) {
            float4 e = __ldg(reinterpret_cast<const float4*>(
                ea + (long long)gc[nv] * 48 + eidx * 4));
            ef[nv][0] = e.x; ef[nv][1] = e.y; ef[nv][2] = e.z; ef[nv][3] = e.w;
        }

#pragma unroll
        for (int half = 0; half < 2; half++) {
            u64 msg[NV][4];
            {
                ulonglong2 ba = ld2(lb + half * 8), bb = ld2(lb + half * 8 + 4);
#pragma unroll
                for (int nv = 0; nv < NV; nv++) {
                    msg[nv][0] = ba.x; msg[nv][1] = ba.y;
                    msg[nv][2] = bb.x; msg[nv][3] = bb.y;
                }
            }
#pragma unroll
            for (int k = 0; k < 4; k++) {
                ulonglong2 wa = ld2(lw + k * 16 + half * 8);
                ulonglong2 wb = ld2(lw + k * 16 + half * 8 + 4);
                u64 wv[4] = {wa.x, wa.y, wb.x, wb.y};
#pragma unroll
                for (int nv = 0; nv < NV; nv++) {
                    u64 ep = pk(ef[nv][k], ef[nv][k]);
#pragma unroll
                    for (int v = 0; v < 4; v++)
                        msg[nv][v] = f2(ep, wv[v], msg[nv][v]);
                }
            }
#pragma unroll
            for (int v = 0; v < 4; v++) {
                int j = half * 4 + v;
#pragma unroll
                for (int nv = 0; nv < NV; nv++) {
                    u64 hs = __shfl_sync(0xffffffffu, h[nv][j], sl);
                    agg[nv][j] = a2(agg[nv][j], r2(a2(msg[nv][v], hs)));
                }
            }
        }
    }

    // in-place: h becomes the MLP input (h + agg), packed
#pragma unroll
    for (int nv = 0; nv < NV; nv++)
#pragma unroll
        for (int j = 0; j < 8; j++) h[nv][j] = a2(h[nv][j], agg[nv][j]);

    u64 out[NV][8];
    {
        ulonglong2 ba = ld2(b2), bb = ld2(b2 + 4), bc = ld2(b2 + 8), bd = ld2(b2 + 12);
#pragma unroll
        for (int nv = 0; nv < NV; nv++) {
            out[nv][0]=ba.x; out[nv][1]=ba.y; out[nv][2]=bb.x; out[nv][3]=bb.y;
            out[nv][4]=bc.x; out[nv][5]=bc.y; out[nv][6]=bd.x; out[nv][7]=bd.y;
        }
    }

    // 8 chunks of 8 hidden units (4 pairs each)
#pragma unroll
    for (int c = 0; c < 8; c++) {
        u64 hid[NV][4];
        {
            ulonglong2 ba = ld2(b1 + c * 8), bb = ld2(b1 + c * 8 + 4);
#pragma unroll
            for (int nv = 0; nv < NV; nv++) {
                hid[nv][0]=ba.x; hid[nv][1]=ba.y; hid[nv][2]=bb.x; hid[nv][3]=bb.y;
            }
        }
#pragma unroll
        for (int jp = 0; jp < 8; jp++) {
            u64 xlo[NV], xhi[NV];
#pragma unroll
            for (int nv = 0; nv < NV; nv++) {
                float a, b; up(h[nv][jp], a, b);
                xlo[nv] = pk(a, a); xhi[nv] = pk(b, b);
            }
#pragma unroll
            for (int t = 0; t < 2; t++) {
                int k = 2 * jp + t;
                const float* r = w1 + k * 64 + c * 8;
                ulonglong2 wa = ld2(r), wb = ld2(r + 4);
                u64 wv[4] = {wa.x, wa.y, wb.x, wb.y};
#pragma unroll
                for (int nv = 0; nv < NV; nv++) {
                    u64 xp = t ? xhi[nv] : xlo[nv];
#pragma unroll
                    for (int v = 0; v < 4; v++)
                        hid[nv][v] = f2(xp, wv[v], hid[nv][v]);
                }
            }
        }
        // relu + second matmul
#pragma unroll
        for (int v = 0; v < 4; v++) {
            float s0[NV], s1[NV];
#pragma unroll
            for (int nv = 0; nv < NV; nv++) {
                float a, b; up(hid[nv][v], a, b);
                s0[nv] = fmaxf(a, 0.f); s1[nv] = fmaxf(b, 0.f);
            }
#pragma unroll
            for (int t = 0; t < 2; t++) {
                int u = c * 8 + 2 * v + t;
                const float* r = w2 + u * 16;
                ulonglong2 wa = ld2(r), wb = ld2(r + 4), wc = ld2(r + 8), wd = ld2(r + 12);
                u64 wv[8] = {wa.x, wa.y, wb.x, wb.y, wc.x, wc.y, wd.x, wd.y};
#pragma unroll
                for (int nv = 0; nv < NV; nv++) {
                    float s = t ? s1[nv] : s0[nv];
                    u64 sp = pk(s, s);
#pragma unroll
                    for (int jj = 0; jj < 8; jj++)
                        out[nv][jj] = f2(sp, wv[jj], out[nv][jj]);
                }
            }
        }
    }

    // LayerNorm (ddof=0) + relu -> back into packed h
#pragma unroll
    for (int nv = 0; nv < NV; nv++) {
        float o[16];
#pragma unroll
        for (int j = 0; j < 8; j++) up(out[nv][j], o[2*j], o[2*j+1]);
        float mean = 0.f;
#pragma unroll
        for (int d = 0; d < 16; d++) mean += o[d];
        mean *= (1.f / 16.f);
        float var = 0.f;
#pragma unroll
        for (int d = 0; d < 16; d++) { float dd = o[d] - mean; var = fmaf(dd, dd, var); }
        var *= (1.f / 16.f);
        float inv = rsqrtf(var + 1e-5f);
#pragma unroll
        for (int j = 0; j < 8; j++)
            h[nv][j] = pk(fmaxf((o[2*j] - mean) * inv, 0.f),
                          fmaxf((o[2*j+1] - mean) * inv, 0.f));
    }
}

__global__ void __launch_bounds__(NTHREADS, 1)
gnn_kernel(Params p)
{
    __shared__ float S[SMEM_FLOATS];

    // stage all weights into shared
    {
        const int sizes[23] = {80,16,256,16, 80,16,256,16,
                               64,16,1024,64,1024,16,
                               64,16,1024,64,1024,16,
                               2048,64,64};
        const int offs[23]  = {JE_W1,JE_B1,JE_W2,JE_B2, MU_W1,MU_B1,MU_W2,MU_B2,
                               L1_W,L1_B,M1_W1,M1_B1,M1_W2,M1_B2,
                               L2_W,L2_B,M2_W1,M2_B1,M2_W2,M2_B2,
                               FC_W1,FC_B1,FC_W2};
        for (int a = 0; a < 23; a++) {
            const float* src = p.w[a];
            float* dst = S + offs[a];
            int n = sizes[a];
            for (int i = threadIdx.x; i < n; i += NTHREADS) dst[i] = src[i];
        }
    }
    __syncthreads();

    int tid = threadIdx.x;
    int lane = tid & 31;
    int node = lane & 3;
    int group = lane >> 2;
    int warpG = (int)((blockIdx.x * (unsigned)NTHREADS + tid) >> 5);

    if (warpG * 32 >= p.G) return;   // warp-uniform

    int base = warpG * 32 + group;
    int gidx[NV], gc[NV];
    bool valid[NV];
#pragma unroll
    for (int nv = 0; nv < NV; nv++) {
        gidx[nv] = base + 8 * nv;
        valid[nv] = gidx[nv] < p.G;
        gc[nv] = valid[nv] ? gidx[nv] : (p.G - 1);
    }

    // ---- heterogeneous encoder ----
    const float* w1p = (node == 3) ? (S + MU_W1) : (S + JE_W1);
    const float* b1p = (node == 3) ? (S + MU_B1) : (S + JE_B1);
    const float* w2p = (node == 3) ? (S + MU_W2) : (S + JE_W2);
    const float* b2p = (node == 3) ? (S + MU_B2) : (S + JE_B2);

    u64 h[NV][8];
    {
        float xin[NV][5];
#pragma unroll
        for (int nv = 0; nv < NV; nv++) {
            const float* xr = p.x + (long long)(gc[nv] * 4 + node) * 5;
#pragma unroll
            for (int k = 0; k < 5; k++) xin[nv][k] = __ldg(xr + k);
        }

        u64 tv[NV][8];
        {
            ulonglong2 ba = ld2(b1p), bb = ld2(b1p + 4), bc = ld2(b1p + 8), bd = ld2(b1p + 12);
#pragma unroll
            for (int nv = 0; nv < NV; nv++) {
                tv[nv][0]=ba.x; tv[nv][1]=ba.y; tv[nv][2]=bb.x; tv[nv][3]=bb.y;
                tv[nv][4]=bc.x; tv[nv][5]=bc.y; tv[nv][6]=bd.x; tv[nv][7]=bd.y;
            }
        }
#pragma unroll
        for (int k = 0; k < 5; k++) {
            const float* r = w1p + k * 16;
            ulonglong2 wa = ld2(r), wb = ld2(r + 4), wc = ld2(r + 8), wd = ld2(r + 12);
            u64 wv[8] = {wa.x, wa.y, wb.x, wb.y, wc.x, wc.y, wd.x, wd.y};
#pragma unroll
            for (int nv = 0; nv < NV; nv++) {
                u64 xp = pk(xin[nv][k], xin[nv][k]);
#pragma unroll
                for (int j = 0; j < 8; j++)
                    tv[nv][j] = f2(xp, wv[j], tv[nv][j]);
            }
        }

        // relu(t) then second encoder matmul into h
        {
            ulonglong2 ba = ld2(b2p), bb = ld2(b2p + 4), bc = ld2(b2p + 8), bd = ld2(b2p + 12);
#pragma unroll
            for (int nv = 0; nv < NV; nv++) {
                h[nv][0]=ba.x; h[nv][1]=ba.y; h[nv][2]=bb.x; h[nv][3]=bb.y;
                h[nv][4]=bc.x; h[nv][5]=bc.y; h[nv][6]=bd.x; h[nv][7]=bd.y;
            }
        }
#pragma unroll
        for (int jp = 0; jp < 8; jp++) {
            u64 xlo[NV], xhi[NV];
#pragma unroll
            for (int nv = 0; nv < NV; nv++) {
                float a, b; up(tv[nv][jp], a, b);
                xlo[nv] = pk(fmaxf(a, 0.f), fmaxf(a, 0.f));
                xhi[nv] = pk(fmaxf(b, 0.f), fmaxf(b, 0.f));
            }
#pragma unroll
            for (int t = 0; t < 2; t++) {
                int k = 2 * jp + t;
                const float* r = w2p + k * 16;
                ulonglong2 wa = ld2(r), wb = ld2(r + 4), wc = ld2(r + 8), wd = ld2(r + 12);
                u64 wv[8] = {wa.x, wa.y, wb.x, wb.y, wc.x, wc.y, wd.x, wd.y};
#pragma unroll
                for (int nv = 0; nv < NV; nv++) {
                    u64 xp = t ? xhi[nv] : xlo[nv];
#pragma unroll
                    for (int j = 0; j < 8; j++)
                        h[nv][j] = f2(xp, wv[j], h[nv][j]);
                }
            }
        }
    }

    // ---- two GINE blocks ----
    gineN(h, lane, node, p.ea, gc,
          S + L1_W, S + L1_B, S + M1_W1, S + M1_B1, S + M1_W2, S + M1_B2);
    gineN(h, lane, node, p.ea, gc,
          S + L2_W, S + L2_B, S + M2_W1, S + M2_B1, S + M2_W2, S + M2_B2);

    const float fcb2 = __ldg(p.w[23]);

    // ---- tail in 2 passes of 2 graphs: pooling + LN + FC head ----
#pragma unroll
    for (int pass = 0; pass < 2; pass++) {
        float g[2][32];
#pragma unroll
        for (int q = 0; q < 2; q++) {
            int nv = 2 * pass + q;
            float hs[16];
#pragma unroll
            for (int j = 0; j < 8; j++) up(h[nv][j], hs[2*j], hs[2*j+1]);
#pragma unroll
            for (int d = 0; d < 16; d++) {
                float s = hs[d];
                s += __shfl_xor_sync(0xffffffffu, s, 1);
                s += __shfl_xor_sync(0xffffffffu, s, 2);
                float mx = hs[d];
                mx = fmaxf(mx, __shfl_xor_sync(0xffffffffu, mx, 1));
                mx = fmaxf(mx, __shfl_xor_sync(0xffffffffu, mx, 2));
                g[q][d] = s * 0.25f;
                g[q][16 + d] = mx;
            }
            float mean = 0.f;
#pragma unroll
            for (int d = 0; d < 32; d++) mean += g[q][d];
            mean *= (1.f / 32.f);
            float var = 0.f;
#pragma unroll
            for (int d = 0; d < 32; d++) { float dd = g[q][d] - mean; var = fmaf(dd, dd, var); }
            var *= (1.f / 32.f);
            float inv = rsqrtf(var + 1e-5f);
#pragma unroll
            for (int d = 0; d < 32; d++) g[q][d] = (g[q][d] - mean) * inv;
        }

        // FC: 32 -> 64 -> 1; each node owns 16 hidden units (packed)
        u64 av[2][8];
        {
            const float* r = S + FC_B1 + node * 16;
            ulonglong2 ba = ld2(r), bb = ld2(r + 4), bc = ld2(r + 8), bd = ld2(r + 12);
#pragma unroll
            for (int q = 0; q < 2; q++) {
                av[q][0]=ba.x; av[q][1]=ba.y; av[q][2]=bb.x; av[q][3]=bb.y;
                av[q][4]=bc.x; av[q][5]=bc.y; av[q][6]=bd.x; av[q][7]=bd.y;
            }
        }
#pragma unroll
        for (int k = 0; k < 32; k++) {
            const float* r = S + FC_W1 + k * 64 + node * 16;
            ulonglong2 wa = ld2(r), wb = ld2(r + 4), wc = ld2(r + 8), wd = ld2(r + 12);
            u64 wv[8] = {wa.x, wa.y, wb.x, wb.y, wc.x, wc.y, wd.x, wd.y};
#pragma unroll
            for (int q = 0; q < 2; q++) {
                u64 gp = pk(g[q][k], g[q][k]);
#pragma unroll
                for (int j = 0; j < 8; j++)
                    av[q][j] = f2(gp, wv[j], av[q][j]);
            }
        }
        float acc[2] = {0.f, 0.f};
#pragma unroll
        for (int j = 0; j < 8; j++) {
            float2 w2v = *reinterpret_cast<const float2*>(S + FC_W2 + node * 16 + 2 * j);
#pragma unroll
            for (int q = 0; q < 2; q++) {
                float a, b; up(av[q][j], a, b);
                acc[q] = fmaf(fmaxf(a, 0.f), w2v.x, acc[q]);
                acc[q] = fmaf(fmaxf(b, 0.f), w2v.y, acc[q]);
            }
        }
#pragma unroll
        for (int q = 0; q < 2; q++) {
            acc[q] += __shfl_xor_sync(0xffffffffu, acc[q], 1);
            acc[q] += __shfl_xor_sync(0xffffffffu, acc[q], 2);
            int nv = 2 * pass + q;
            if (node == 0 && valid[nv])
                p.out[gidx[nv]] = acc[q] + fcb2;
        }
    }
}

extern "C" void kernel_launch(void* const* d_in, const int* in_sizes, int n_in,
                              void* d_out, int out_size)
{
    Params p;
    p.x  = (const float*)d_in[0];
    p.ea = (const float*)d_in[1];
    for (int i = 0; i < 24; i++) p.w[i] = (const float*)d_in[2 + i];
    p.out = (float*)d_out;
    p.G = in_sizes[0] / 20;            // x is [G*4, 5]

    // 32 graphs per warp, 8 warps per block -> 256 graphs per block
    int blocks = (p.G + 255) / 256;
    if (blocks < 1) blocks = 1;
    gnn_kernel<<<blocks, NTHREADS>>>(p);
}

// round 7
// speedup vs baseline: 1.3244x; 1.3244x over previous
#include <cuda_runtime.h>

// Fixed problem structure:
//   4 nodes/graph (nodes 0..2 = jet, node 3 = muon)
//   12 directed edges/graph, edge (i,j) index within graph = 3*i + (j - (j>i))
//   H = 16, MH = 64.
// Mapping: warp = 8 groups of 4 lanes; group j handles graphs base+j and base+j+8
// (NV=2, 128-reg / 2-blocks-per-SM sweet spot). All inner products use packed
// f32x2 FFMA along the output-dim axis. Message-stage weights are hoisted across
// the 3 neighbors (12 FFMA2 per 16B load there); pooling shuffles are packed u64.

#define NTHREADS 256
#define NV 2

typedef unsigned long long u64;

// ---- shared memory layout (floats) ----
#define JE_W1 0      // 80
#define JE_B1 80     // 16
#define JE_W2 96     // 256
#define JE_B2 352    // 16
#define MU_W1 368    // 80
#define MU_B1 448    // 16
#define MU_W2 464    // 256
#define MU_B2 720    // 16
#define L1_W  736    // 64
#define L1_B  800    // 16
#define M1_W1 816    // 1024
#define M1_B1 1840   // 64
#define M1_W2 1904   // 1024
#define M1_B2 2928   // 16
#define L2_W  2944   // 64
#define L2_B  3008   // 16
#define M2_W1 3024   // 1024
#define M2_B1 4048   // 64
#define M2_W2 4112   // 1024
#define M2_B2 5136   // 16
#define FC_W1 5152   // 2048
#define FC_B1 7200   // 64
#define FC_W2 7264   // 64
#define SMEM_FLOATS 7328

struct Params {
    const float* x;
    const float* ea;
    const float* w[24];   // je_w1..fc_b2 in metadata order
    float* out;
    int G;
};

// ---- packed f32x2 helpers ----
__device__ __forceinline__ u64 pk(float lo, float hi) {
    u64 r; asm("mov.b64 %0,{%1,%2};" : "=l"(r) : "f"(lo), "f"(hi)); return r;
}
__device__ __forceinline__ void up(u64 v, float& lo, float& hi) {
    asm("mov.b64 {%0,%1},%2;" : "=f"(lo), "=f"(hi) : "l"(v));
}
__device__ __forceinline__ u64 f2(u64 a, u64 b, u64 c) {  // a*b+c elementwise
    u64 d; asm("fma.rn.f32x2 %0,%1,%2,%3;" : "=l"(d) : "l"(a), "l"(b), "l"(c)); return d;
}
__device__ __forceinline__ u64 a2(u64 a, u64 b) {
    u64 d; asm("add.rn.f32x2 %0,%1,%2;" : "=l"(d) : "l"(a), "l"(b)); return d;
}
__device__ __forceinline__ u64 r2(u64 a) {   // relu both halves
    float l, h; up(a, l, h);
    return pk(fmaxf(l, 0.f), fmaxf(h, 0.f));
}
__device__ __forceinline__ ulonglong2 ld2(const float* p) {  // LDS.128 -> 2 packed pairs
    return *reinterpret_cast<const ulonglong2*>(p);
}

// one GINE layer + LN + relu for NV graphs; h (packed dim-pairs) updated in place.
__device__ __forceinline__ void gineN(
    u64 h[NV][8], int lane, int node,
    const float* __restrict__ ea, const int* gc,
    const float* lw, const float* lb,
    const float* w1, const float* b1,
    const float* w2, const float* b2)
{
    u64 agg[NV][8];
#pragma unroll
    for (int nv = 0; nv < NV; nv++)
#pragma unroll
        for (int j = 0; j < 8; j++) agg[nv][j] = 0ull;

    // ---- message stage: weights hoisted across all 3 neighbors ----
    float ef[NV][3][4];
    int slv[3];
#pragma unroll
    for (int m = 1; m < 4; m++) {
        int src = (node + m) & 3;
        int eidx = src * 3 + node - (node > src ? 1 : 0);
        slv[m - 1] = (lane & ~3) | src;
#pragma unroll
        for (int nv = 0; nv < NV; nv++) {
            float4 e = __ldg(reinterpret_cast<const float4*>(
                ea + (long long)gc[nv] * 48 + eidx * 4));
            ef[nv][m-1][0] = e.x; ef[nv][m-1][1] = e.y;
            ef[nv][m-1][2] = e.z; ef[nv][m-1][3] = e.w;
        }
    }

#pragma unroll
    for (int v = 0; v < 4; v++) {           // chunk: dim-pairs 2v, 2v+1
        u64 msg[NV][3][2];
        {
            ulonglong2 b = ld2(lb + 4 * v);
#pragma unroll
            for (int nv = 0; nv < NV; nv++)
#pragma unroll
                for (int mm = 0; mm < 3; mm++) {
                    msg[nv][mm][0] = b.x; msg[nv][mm][1] = b.y;
                }
        }
#pragma unroll
        for (int k = 0; k < 4; k++) {
            ulonglong2 w = ld2(lw + k * 16 + 4 * v);
#pragma unroll
            for (int mm = 0; mm < 3; mm++)
#pragma unroll
                for (int nv = 0; nv < NV; nv++) {
                    u64 ep = pk(ef[nv][mm][k], ef[nv][mm][k]);
                    msg[nv][mm][0] = f2(ep, w.x, msg[nv][mm][0]);
                    msg[nv][mm][1] = f2(ep, w.y, msg[nv][mm][1]);
                }
        }
#pragma unroll
        for (int mm = 0; mm < 3; mm++) {
            int sl = slv[mm];
#pragma unroll
            for (int nv = 0; nv < NV; nv++)
#pragma unroll
                for (int pr = 0; pr < 2; pr++) {
                    int j = 2 * v + pr;
                    u64 hs = __shfl_sync(0xffffffffu, h[nv][j], sl);
                    agg[nv][j] = a2(agg[nv][j], r2(a2(msg[nv][mm][pr], hs)));
                }
        }
    }

    // in-place: h becomes the MLP input (h + agg), packed
#pragma unroll
    for (int nv = 0; nv < NV; nv++)
#pragma unroll
        for (int j = 0; j < 8; j++) h[nv][j] = a2(h[nv][j], agg[nv][j]);

    u64 out[NV][8];
    {
        ulonglong2 ba = ld2(b2), bb = ld2(b2 + 4), bc = ld2(b2 + 8), bd = ld2(b2 + 12);
#pragma unroll
        for (int nv = 0; nv < NV; nv++) {
            out[nv][0]=ba.x; out[nv][1]=ba.y; out[nv][2]=bb.x; out[nv][3]=bb.y;
            out[nv][4]=bc.x; out[nv][5]=bc.y; out[nv][6]=bd.x; out[nv][7]=bd.y;
        }
    }

    // 8 chunks of 8 hidden units (4 pairs each)
#pragma unroll
    for (int c = 0; c < 8; c++) {
        u64 hid[NV][4];
        {
            ulonglong2 ba = ld2(b1 + c * 8), bb = ld2(b1 + c * 8 + 4);
#pragma unroll
            for (int nv = 0; nv < NV; nv++) {
                hid[nv][0]=ba.x; hid[nv][1]=ba.y; hid[nv][2]=bb.x; hid[nv][3]=bb.y;
            }
        }
#pragma unroll
        for (int jp = 0; jp < 8; jp++) {
            u64 xlo[NV], xhi[NV];
#pragma unroll
            for (int nv = 0; nv < NV; nv++) {
                float a, b; up(h[nv][jp], a, b);
                xlo[nv] = pk(a, a); xhi[nv] = pk(b, b);
            }
#pragma unroll
            for (int t = 0; t < 2; t++) {
                int k = 2 * jp + t;
                const float* r = w1 + k * 64 + c * 8;
                ulonglong2 wa = ld2(r), wb = ld2(r + 4);
                u64 wv[4] = {wa.x, wa.y, wb.x, wb.y};
#pragma unroll
                for (int nv = 0; nv < NV; nv++) {
                    u64 xp = t ? xhi[nv] : xlo[nv];
#pragma unroll
                    for (int v = 0; v < 4; v++)
                        hid[nv][v] = f2(xp, wv[v], hid[nv][v]);
                }
            }
        }
        // relu + second matmul
#pragma unroll
        for (int v = 0; v < 4; v++) {
            float s0[NV], s1[NV];
#pragma unroll
            for (int nv = 0; nv < NV; nv++) {
                float a, b; up(hid[nv][v], a, b);
                s0[nv] = fmaxf(a, 0.f); s1[nv] = fmaxf(b, 0.f);
            }
#pragma unroll
            for (int t = 0; t < 2; t++) {
                int u = c * 8 + 2 * v + t;
                const float* r = w2 + u * 16;
                ulonglong2 wa = ld2(r), wb = ld2(r + 4), wc = ld2(r + 8), wd = ld2(r + 12);
                u64 wv[8] = {wa.x, wa.y, wb.x, wb.y, wc.x, wc.y, wd.x, wd.y};
#pragma unroll
                for (int nv = 0; nv < NV; nv++) {
                    float s = t ? s1[nv] : s0[nv];
                    u64 sp = pk(s, s);
#pragma unroll
                    for (int jj = 0; jj < 8; jj++)
                        out[nv][jj] = f2(sp, wv[jj], out[nv][jj]);
                }
            }
        }
    }

    // LayerNorm (ddof=0) + relu -> back into packed h
#pragma unroll
    for (int nv = 0; nv < NV; nv++) {
        float o[16];
#pragma unroll
        for (int j = 0; j < 8; j++) up(out[nv][j], o[2*j], o[2*j+1]);
        float mean = 0.f;
#pragma unroll
        for (int d = 0; d < 16; d++) mean += o[d];
        mean *= (1.f / 16.f);
        float var = 0.f;
#pragma unroll
        for (int d = 0; d < 16; d++) { float dd = o[d] - mean; var = fmaf(dd, dd, var); }
        var *= (1.f / 16.f);
        float inv = rsqrtf(var + 1e-5f);
#pragma unroll
        for (int j = 0; j < 8; j++)
            h[nv][j] = pk(fmaxf((o[2*j] - mean) * inv, 0.f),
                          fmaxf((o[2*j+1] - mean) * inv, 0.f));
    }
}

__global__ void __launch_bounds__(NTHREADS, 2)
gnn_kernel(Params p)
{
    __shared__ float S[SMEM_FLOATS];

    // stage all weights into shared
    {
        const int sizes[23] = {80,16,256,16, 80,16,256,16,
                               64,16,1024,64,1024,16,
                               64,16,1024,64,1024,16,
                               2048,64,64};
        const int offs[23]  = {JE_W1,JE_B1,JE_W2,JE_B2, MU_W1,MU_B1,MU_W2,MU_B2,
                               L1_W,L1_B,M1_W1,M1_B1,M1_W2,M1_B2,
                               L2_W,L2_B,M2_W1,M2_B1,M2_W2,M2_B2,
                               FC_W1,FC_B1,FC_W2};
        for (int a = 0; a < 23; a++) {
            const float* src = p.w[a];
            float* dst = S + offs[a];
            int n = sizes[a];
            for (int i = threadIdx.x; i < n; i += NTHREADS) dst[i] = src[i];
        }
    }
    __syncthreads();

    int tid = threadIdx.x;
    int lane = tid & 31;
    int node = lane & 3;
    int group = lane >> 2;
    int warpG = (int)((blockIdx.x * (unsigned)NTHREADS + tid) >> 5);

    if (warpG * 16 >= p.G) return;   // warp-uniform

    int base = warpG * 16 + group;
    int gidx[NV], gc[NV];
    bool valid[NV];
#pragma unroll
    for (int nv = 0; nv < NV; nv++) {
        gidx[nv] = base + 8 * nv;
        valid[nv] = gidx[nv] < p.G;
        gc[nv] = valid[nv] ? gidx[nv] : (p.G - 1);
    }

    // ---- heterogeneous encoder ----
    const float* w1p = (node == 3) ? (S + MU_W1) : (S + JE_W1);
    const float* b1p = (node == 3) ? (S + MU_B1) : (S + JE_B1);
    const float* w2p = (node == 3) ? (S + MU_W2) : (S + JE_W2);
    const float* b2p = (node == 3) ? (S + MU_B2) : (S + JE_B2);

    u64 h[NV][8];
    {
        float xin[NV][5];
#pragma unroll
        for (int nv = 0; nv < NV; nv++) {
            const float* xr = p.x + (long long)(gc[nv] * 4 + node) * 5;
#pragma unroll
            for (int k = 0; k < 5; k++) xin[nv][k] = __ldg(xr + k);
        }

        u64 tv[NV][8];
        {
            ulonglong2 ba = ld2(b1p), bb = ld2(b1p + 4), bc = ld2(b1p + 8), bd = ld2(b1p + 12);
#pragma unroll
            for (int nv = 0; nv < NV; nv++) {
                tv[nv][0]=ba.x; tv[nv][1]=ba.y; tv[nv][2]=bb.x; tv[nv][3]=bb.y;
                tv[nv][4]=bc.x; tv[nv][5]=bc.y; tv[nv][6]=bd.x; tv[nv][7]=bd.y;
            }
        }
#pragma unroll
        for (int k = 0; k < 5; k++) {
            const float* r = w1p + k * 16;
            ulonglong2 wa = ld2(r), wb = ld2(r + 4), wc = ld2(r + 8), wd = ld2(r + 12);
            u64 wv[8] = {wa.x, wa.y, wb.x, wb.y, wc.x, wc.y, wd.x, wd.y};
#pragma unroll
            for (int nv = 0; nv < NV; nv++) {
                u64 xp = pk(xin[nv][k], xin[nv][k]);
#pragma unroll
                for (int j = 0; j < 8; j++)
                    tv[nv][j] = f2(xp, wv[j], tv[nv][j]);
            }
        }

        // relu(t) then second encoder matmul into h
        {
            ulonglong2 ba = ld2(b2p), bb = ld2(b2p + 4), bc = ld2(b2p + 8), bd = ld2(b2p + 12);
#pragma unroll
            for (int nv = 0; nv < NV; nv++) {
                h[nv][0]=ba.x; h[nv][1]=ba.y; h[nv][2]=bb.x; h[nv][3]=bb.y;
                h[nv][4]=bc.x; h[nv][5]=bc.y; h[nv][6]=bd.x; h[nv][7]=bd.y;
            }
        }
#pragma unroll
        for (int jp = 0; jp < 8; jp++) {
            u64 xlo[NV], xhi[NV];
#pragma unroll
            for (int nv = 0; nv < NV; nv++) {
                float a, b; up(tv[nv][jp], a, b);
                xlo[nv] = pk(fmaxf(a, 0.f), fmaxf(a, 0.f));
                xhi[nv] = pk(fmaxf(b, 0.f), fmaxf(b, 0.f));
            }
#pragma unroll
            for (int t = 0; t < 2; t++) {
                int k = 2 * jp + t;
                const float* r = w2p + k * 16;
                ulonglong2 wa = ld2(r), wb = ld2(r + 4), wc = ld2(r + 8), wd = ld2(r + 12);
                u64 wv[8] = {wa.x, wa.y, wb.x, wb.y, wc.x, wc.y, wd.x, wd.y};
#pragma unroll
                for (int nv = 0; nv < NV; nv++) {
                    u64 xp = t ? xhi[nv] : xlo[nv];
#pragma unroll
                    for (int j = 0; j < 8; j++)
                        h[nv][j] = f2(xp, wv[j], h[nv][j]);
                }
            }
        }
    }

    // ---- two GINE blocks ----
    gineN(h, lane, node, p.ea, gc,
          S + L1_W, S + L1_B, S + M1_W1, S + M1_B1, S + M1_W2, S + M1_B2);
    gineN(h, lane, node, p.ea, gc,
          S + L2_W, S + L2_B, S + M2_W1, S + M2_B1, S + M2_W2, S + M2_B2);

    // ---- pooling (mean + max over the 4 lanes of the graph, packed shfl) + LN ----
    float g[NV][32];
#pragma unroll
    for (int nv = 0; nv < NV; nv++) {
#pragma unroll
        for (int j = 0; j < 8; j++) {
            u64 s = h[nv][j];
            s = a2(s, __shfl_xor_sync(0xffffffffu, s, 1));
            s = a2(s, __shfl_xor_sync(0xffffffffu, s, 2));
            float sa, sb; up(s, sa, sb);
            g[nv][2*j]   = sa * 0.25f;
            g[nv][2*j+1] = sb * 0.25f;

            u64 mx = h[nv][j];
            {
                u64 o1 = __shfl_xor_sync(0xffffffffu, mx, 1);
                float a0, b0, a1, b1; up(mx, a0, b0); up(o1, a1, b1);
                mx = pk(fmaxf(a0, a1), fmaxf(b0, b1));
                u64 o2 = __shfl_xor_sync(0xffffffffu, mx, 2);
                up(mx, a0, b0); up(o2, a1, b1);
                g[nv][16 + 2*j]   = fmaxf(a0, a1);
                g[nv][16 + 2*j+1] = fmaxf(b0, b1);
            }
        }
        float mean = 0.f;
#pragma unroll
        for (int d = 0; d < 32; d++) mean += g[nv][d];
        mean *= (1.f / 32.f);
        float var = 0.f;
#pragma unroll
        for (int d = 0; d < 32; d++) { float dd = g[nv][d] - mean; var = fmaf(dd, dd, var); }
        var *= (1.f / 32.f);
        float inv = rsqrtf(var + 1e-5f);
#pragma unroll
        for (int d = 0; d < 32; d++) g[nv][d] = (g[nv][d] - mean) * inv;
    }

    // ---- FC head: 32 -> 64 -> 1; each node owns 16 hidden units (packed) ----
    u64 av[NV][8];
    {
        const float* r = S + FC_B1 + node * 16;
        ulonglong2 ba = ld2(r), bb = ld2(r + 4), bc = ld2(r + 8), bd = ld2(r + 12);
#pragma unroll
        for (int nv = 0; nv < NV; nv++) {
            av[nv][0]=ba.x; av[nv][1]=ba.y; av[nv][2]=bb.x; av[nv][3]=bb.y;
            av[nv][4]=bc.x; av[nv][5]=bc.y; av[nv][6]=bd.x; av[nv][7]=bd.y;
        }
    }
#pragma unroll
    for (int k = 0; k < 32; k++) {
        const float* r = S + FC_W1 + k * 64 + node * 16;
        ulonglong2 wa = ld2(r), wb = ld2(r + 4), wc = ld2(r + 8), wd = ld2(r + 12);
        u64 wv[8] = {wa.x, wa.y, wb.x, wb.y, wc.x, wc.y, wd.x, wd.y};
#pragma unroll
        for (int nv = 0; nv < NV; nv++) {
            u64 gp = pk(g[nv][k], g[nv][k]);
#pragma unroll
            for (int j = 0; j < 8; j++)
                av[nv][j] = f2(gp, wv[j], av[nv][j]);
        }
    }
    float acc[NV] = {0.f, 0.f};
#pragma unroll
    for (int j = 0; j < 8; j++) {
        float2 w2v = *reinterpret_cast<const float2*>(S + FC_W2 + node * 16 + 2 * j);
#pragma unroll
        for (int nv = 0; nv < NV; nv++) {
            float a, b; up(av[nv][j], a, b);
            acc[nv] = fmaf(fmaxf(a, 0.f), w2v.x, acc[nv]);
            acc[nv] = fmaf(fmaxf(b, 0.f), w2v.y, acc[nv]);
        }
    }
    const float fcb2 = __ldg(p.w[23]);
#pragma unroll
    for (int nv = 0; nv < NV; nv++) {
        acc[nv] += __shfl_xor_sync(0xffffffffu, acc[nv], 1);
        acc[nv] += __shfl_xor_sync(0xffffffffu, acc[nv], 2);
        if (node == 0 && valid[nv])
            p.out[gidx[nv]] = acc[nv] + fcb2;
    }
}

extern "C" void kernel_launch(void* const* d_in, const int* in_sizes, int n_in,
                              void* d_out, int out_size)
{
    Params p;
    p.x  = (const float*)d_in[0];
    p.ea = (const float*)d_in[1];
    for (int i = 0; i < 24; i++) p.w[i] = (const float*)d_in[2 + i];
    p.out = (float*)d_out;
    p.G = in_sizes[0] / 20;            // x is [G*4, 5]

    // 16 graphs per warp, 8 warps per block -> 128 graphs per block
    int blocks = (p.G + 127) / 128;
    if (blocks < 1) blocks = 1;
    gnn_kernel<<<blocks, NTHREADS>>>(p);
}